// round 6
// baseline (speedup 1.0000x reference)
#include <cuda_runtime.h>

#define TM1 262143            // T-1 output timesteps (real steps t=0..262142)
#define NTILES 4096           // 4096*64 = 262144 steps (1 pad step)
#define TILE 64
#define PRE_TCHUNK 128
#define CHUNK 256             // stage-B chunk (steps)
#define NCHUNKS ((TM1 + CHUNK - 1) / CHUNK)   // 1024
#define NB 6                  // stage-B helper CTAs
#define GRID_MEGA (2 + NB)

typedef unsigned long long ull;

// Scratch. Padded: recurrences run 262144 steps and prefetch +2 ahead.
// Unwritten tails stay zero (device globals are zero-initialized once; nothing writes them).
__device__ float g_pre0[(size_t)(TM1 + 67) * 256];
__device__ float g_h0[(size_t)(TM1 + 2) * 64];
__device__ float g_pre1[(size_t)(TM1 + 67) * 256];
__device__ float g_h2[(size_t)(TM1 + 2) * 64];
__device__ int   g_progA;
__device__ int   g_chunk_done[NCHUNKS];

// ---------------- fast math helpers ----------------
__device__ __forceinline__ void ffma2(ull& acc, ull a, ull b) {
    asm("fma.rn.f32x2 %0, %1, %2, %0;" : "+l"(acc) : "l"(a), "l"(b));
}
__device__ __forceinline__ float hsum4(ull a0, ull a1, ull a2, ull a3) {
    ull s0, s1, s;
    asm("add.rn.f32x2 %0, %1, %2;" : "=l"(s0) : "l"(a0), "l"(a1));
    asm("add.rn.f32x2 %0, %1, %2;" : "=l"(s1) : "l"(a2), "l"(a3));
    asm("add.rn.f32x2 %0, %1, %2;" : "=l"(s)  : "l"(s0), "l"(s1));
    float lo, hi;
    asm("mov.b64 {%0,%1}, %2;" : "=f"(lo), "=f"(hi) : "l"(s));
    return lo + hi;
}
__device__ __forceinline__ float fast_ex2(float x) {
    float r; asm("ex2.approx.f32 %0, %1;" : "=f"(r) : "f"(x)); return r;
}
__device__ __forceinline__ float fast_rcp(float x) {
    float r; asm("rcp.approx.f32 %0, %1;" : "=f"(r) : "f"(x)); return r;
}

// ---------------- cross-CTA sync ----------------
__device__ __forceinline__ int ld_acq(const int* p) {
    int v; asm volatile("ld.global.acquire.gpu.b32 %0, [%1];" : "=r"(v) : "l"(p)); return v;
}
__device__ __forceinline__ void st_rel(int* p, int v) {
    asm volatile("st.global.release.gpu.b32 [%0], %1;" :: "l"(p), "r"(v) : "memory");
}

// 64-dot of packed weight row w[32] against 16B-aligned smem vector (broadcast loads).
__device__ __forceinline__ float dot64(const ull* __restrict__ w, const float* __restrict__ hvec) {
    ull a0 = 0ull, a1 = 0ull, a2 = 0ull, a3 = 0ull;
    const ulonglong2* hp = (const ulonglong2*)hvec;
#pragma unroll
    for (int i = 0; i < 16; i += 2) {
        ulonglong2 va = hp[i];
        ulonglong2 vb = hp[i + 1];
        ffma2(a0, w[2 * i],     va.x);
        ffma2(a1, w[2 * i + 1], va.y);
        ffma2(a2, w[2 * i + 2], vb.x);
        ffma2(a3, w[2 * i + 3], vb.y);
    }
    return hsum4(a0, a1, a2, a3);
}

// ---------------- init: reset cross-CTA sync state (graph replays!) ----------------
__global__ void init_sync_kernel() {
    int i = blockIdx.x * blockDim.x + threadIdx.x;
    if (i == 0) g_progA = 0;
    if (i < NCHUNKS) g_chunk_done[i] = 0;
}

// ---------------- phase 1: layer0 input-side preactivations ----------------
__global__ __launch_bounds__(256)
void pre0_kernel(const float* __restrict__ y,
                 const float* __restrict__ Wih0,
                 const float* __restrict__ bih0,
                 const float* __restrict__ bhh0)
{
    __shared__ float sy[PRE_TCHUNK + 8];
    const int r = threadIdx.x;
    const int t0 = blockIdx.x * PRE_TCHUNK;
    int t1 = t0 + PRE_TCHUNK; if (t1 > TM1) t1 = TM1;

    for (int i = r; i < PRE_TCHUNK + 5; i += 256) {
        int idx = t0 + i;                    // padded index
        sy[i] = (idx < 5) ? 1.0f : y[idx - 5];
    }

    float w[6];
#pragma unroll
    for (int j = 0; j < 6; j++) w[j] = Wih0[r * 6 + j];
    const float b = bih0[r] + bhh0[r];
    __syncthreads();

    for (int t = t0; t < t1; t++) {
        float acc = b;
#pragma unroll
        for (int j = 0; j < 6; j++)
            acc = fmaf(w[j], sy[t - t0 + j], acc);
        g_pre0[(size_t)t * 256 + r] = acc;
    }
}

// ============ recurrence core (branch-free inner loop) ============
#define LOG2E    1.4426950408889634f
#define TWOLOG2E 2.8853900817779268f

// One LSTM step: read shb[RD], write shb[WR]. NO branches: every lane stores
// (all 4 gate-lanes of a unit compute identical h; same-address writes collapse).
template<int RD, int WR>
__device__ __forceinline__ void lstm_step(
    const ull* __restrict__ w, float (&shb)[2][64], float& c,
    float& p0, float& p1, const float* __restrict__ preNext,
    float* __restrict__ hOut,
    float am, float aa, float ab, int u8, int u)
{
    const float p2 = *preNext;                     // prefetch t+2 (LDG, covered 2 steps ahead)

    // dot with p0 folded into accumulator a0's low half
    ull a0, a1 = 0ull, a2 = 0ull, a3 = 0ull;
    asm("mov.b64 %0, {%1, %2};" : "=l"(a0) : "f"(p0), "f"(0.0f));
    const ulonglong2* hp = (const ulonglong2*)shb[RD];
#pragma unroll
    for (int i = 0; i < 16; i += 2) {
        ulonglong2 va = hp[i];
        ulonglong2 vb = hp[i + 1];
        ffma2(a0, w[2 * i],     va.x);
        ffma2(a1, w[2 * i + 1], va.y);
        ffma2(a2, w[2 * i + 2], vb.x);
        ffma2(a3, w[2 * i + 3], vb.y);
    }
    const float v = hsum4(a0, a1, a2, a3);

    // gate nonlinearity: 1 ex2 + 1 rcp covers all 4 gate types (per-lane consts)
    const float e   = fast_ex2(am * v);
    const float act = fmaf(ab, fast_rcp(e + 1.0f), aa);
    // gather all 4 gates of unit u (all lanes redundant -> zero divergence)
    const float gi = __shfl_sync(0xffffffffu, act, u8);
    const float gf = __shfl_sync(0xffffffffu, act, u8 + 8);
    const float gg = __shfl_sync(0xffffffffu, act, u8 + 16);
    const float go = __shfl_sync(0xffffffffu, act, u8 + 24);
    c = fmaf(gf, c, gi * gg);
    const float th = fmaf(-2.0f, fast_rcp(fast_ex2(TWOLOG2E * c) + 1.0f), 1.0f);
    const float h  = go * th;

    shb[WR][u] = h;        // unconditional: disjoint buffer, duplicate-addr collapse
    *hOut = h;             // unconditional STG, 4 lanes same addr, same value
    __syncthreads();       // one barrier per step
    p0 = p1; p1 = p2;
}

template<bool IS_C>
__device__ void recurrence(const float* __restrict__ Whh,
                           const float* __restrict__ preBuf,
                           float* __restrict__ hTrace)
{
    __shared__ __align__(16) float shb[2][64];
    const int tid = threadIdx.x;
    const int wv  = tid >> 5;
    const int l   = tid & 31;
    const int g   = l >> 3;
    const int u8  = l & 7;
    const int u   = 8 * wv + u8;
    const int r   = 64 * g + u;

    ull w[32];
    {
        const ull* p = (const ull*)(Whh + r * 64);
#pragma unroll
        for (int i = 0; i < 32; i++) w[i] = p[i];
    }
    const float am = (g == 2) ? TWOLOG2E : -LOG2E;
    const float aa = (g == 2) ? 1.0f : 0.0f;
    const float ab = (g == 2) ? -2.0f : 1.0f;

    if (l < 8) shb[0][u] = 0.0f;
    float c = 0.0f;

    if (IS_C) {  // wait for first pre1 chunk
        while (ld_acq(&g_chunk_done[0]) == 0) __nanosleep(256);
    }
    float p0 = preBuf[r];
    float p1 = preBuf[256 + r];
    __syncthreads();

    const float* pp = preBuf + 2 * 256 + r;   // address of pre[t+2] for t=0
    float* hp = hTrace + u;                   // address of hTrace[t=0]

    for (int tile = 0; tile < NTILES; tile++) {
        if (IS_C) {
            // ensure pre1 available through tile_end+2 (chunk granularity)
            int ch = (tile * TILE + TILE + 1) >> 8;
            if (ch > NCHUNKS - 1) ch = NCHUNKS - 1;
            while (ld_acq(&g_chunk_done[ch]) == 0) __nanosleep(128);
        }
        // 64 steps, unrolled in pairs -> compile-time double-buffer indices
#pragma unroll 1
        for (int s = 0; s < TILE; s += 2) {
            lstm_step<0, 1>(w, shb, c, p0, p1, pp,       hp,      am, aa, ab, u8, u);
            lstm_step<1, 0>(w, shb, c, p0, p1, pp + 256, hp + 64, am, aa, ab, u8, u);
            pp += 512; hp += 128;
        }
        if (!IS_C) {
            if (tid == 0) {          // publish progress (bar-cumulativity + fence.gpu)
                __threadfence();
                st_rel(&g_progA, (tile + 1) * TILE);
            }
        }
    }
}

// ---------------- stage B: pre1[t] = b1 + W_ih1 . h0[t]  (NB trailing CTAs) ----------------
__device__ void stageB(int helper,
                       const float* __restrict__ Wih1,
                       const float* __restrict__ bih1,
                       const float* __restrict__ bhh1)
{
    __shared__ __align__(16) float sh[64 * 64];   // 64-step tile of h0
    const int r = threadIdx.x;

    ull w[32];
    {
        const ull* p = (const ull*)(Wih1 + r * 64);
#pragma unroll
        for (int i = 0; i < 32; i++) w[i] = p[i];
    }
    const float b1 = bih1[r] + bhh1[r];

    for (int c = helper; c < NCHUNKS; c += NB) {
        const int t0 = c * CHUNK;
        int t1 = t0 + CHUNK; if (t1 > TM1) t1 = TM1;

        while (ld_acq(&g_progA) < t1) __nanosleep(256);

        for (int tb = t0; tb < t1; tb += 64) {
            const int cnt = min(64, t1 - tb);
            __syncthreads();
            for (int i = r; i < cnt * 64; i += 256)
                sh[i] = g_h0[(size_t)tb * 64 + i];
            __syncthreads();
            for (int tt = 0; tt < cnt; tt++)
                g_pre1[(size_t)(tb + tt) * 256 + r] = b1 + dot64(w, sh + tt * 64);
        }
        __syncthreads();
        if (r == 0) { __threadfence(); st_rel(&g_chunk_done[c], 1); }
    }
}

// ---------------- pipelined serial phase: 8 co-resident CTAs ----------------
__global__ __launch_bounds__(256, 1)
void lstm_pipe_kernel(const float* __restrict__ Whh0,
                      const float* __restrict__ Wih1,
                      const float* __restrict__ Whh1,
                      const float* __restrict__ bih1,
                      const float* __restrict__ bhh1)
{
    if (blockIdx.x == 0)       recurrence<false>(Whh0, g_pre0, g_h0);
    else if (blockIdx.x == 1)  recurrence<true >(Whh1, g_pre1, g_h2);
    else                       stageB(blockIdx.x - 2, Wih1, bih1, bhh1);
}

// ---------------- phase 3: parallel FC head ----------------
__global__ __launch_bounds__(256)
void fc_kernel(const float* __restrict__ Wfc,
               const float* __restrict__ bfc,
               float* __restrict__ out)
{
    __shared__ float sWT[64 * 64];
    __shared__ float sh[64 * 64];

    const int tid = threadIdx.x;
    for (int i = tid; i < 4096; i += 256) {
        int n = i >> 6, k = i & 63;
        sWT[k * 64 + n] = Wfc[i];
    }
    const int tbase = blockIdx.x * 64;
    for (int i = tid; i < 4096; i += 256) {
        int tt = i >> 6, k = i & 63;
        int t = tbase + tt;
        sh[i] = (t < TM1) ? g_h2[(size_t)t * 64 + k] : 0.0f;
    }
    __syncthreads();

    const int n = tid & 63;
    const float bb = bfc[n];
    for (int tt = tid >> 6; tt < 64; tt += 4) {
        const int t = tbase + tt;
        if (t >= TM1) break;
        float acc = bb;
#pragma unroll
        for (int k = 0; k < 64; k++)
            acc = fmaf(sh[tt * 64 + k], sWT[k * 64 + n], acc);
        out[(size_t)t * 64 + n] = acc;
    }
}

// ---------------- launch ----------------
extern "C" void kernel_launch(void* const* d_in, const int* in_sizes, int n_in,
                              void* d_out, int out_size)
{
    const float* y    = (const float*)d_in[0];
    const float* Wih0 = (const float*)d_in[1];
    const float* Whh0 = (const float*)d_in[2];
    const float* bih0 = (const float*)d_in[3];
    const float* bhh0 = (const float*)d_in[4];
    const float* Wih1 = (const float*)d_in[5];
    const float* Whh1 = (const float*)d_in[6];
    const float* bih1 = (const float*)d_in[7];
    const float* bhh1 = (const float*)d_in[8];
    const float* Wfc  = (const float*)d_in[9];
    const float* bfc  = (const float*)d_in[10];
    float* out = (float*)d_out;

    init_sync_kernel<<<4, 256>>>();
    const int preblocks = (TM1 + PRE_TCHUNK - 1) / PRE_TCHUNK;
    pre0_kernel<<<preblocks, 256>>>(y, Wih0, bih0, bhh0);
    lstm_pipe_kernel<<<GRID_MEGA, 256>>>(Whh0, Wih1, Whh1, bih1, bhh1);
    fc_kernel<<<(TM1 + 63) / 64, 256>>>(Wfc, bfc, out);
}

// round 7
// speedup vs baseline: 1.1372x; 1.1372x over previous
#include <cuda_runtime.h>

#define TM1 262143           // T-1 output timesteps
#define PRE_TCHUNK 128
#define CHUNK 256            // stage-B chunk (steps)
#define NCHUNKS ((TM1 + CHUNK - 1) / CHUNK)   // 1024
#define NB 6                 // stage-B helper CTAs
#define GRID_MEGA (2 + NB)

typedef unsigned long long ull;

// Scratch (+pad so depth-2 prefetch never clamps; unwritten tails stay zero)
__device__ float g_pre0[(size_t)(TM1 + 4) * 256];
__device__ float g_h0[(size_t)TM1 * 64];
__device__ float g_pre1[(size_t)(TM1 + 4) * 256];
__device__ float g_h2[(size_t)TM1 * 64];
__device__ int   g_progA;
__device__ int   g_chunk_done[NCHUNKS];

// ---------------- fast math helpers ----------------
__device__ __forceinline__ void ffma2(ull& acc, ull a, ull b) {
    asm("fma.rn.f32x2 %0, %1, %2, %0;" : "+l"(acc) : "l"(a), "l"(b));
}
__device__ __forceinline__ ull packf2(float x, float y) {
    ull r; asm("mov.b64 %0, {%1, %2};" : "=l"(r) : "f"(x), "f"(y)); return r;
}
__device__ __forceinline__ float hsum4(ull a0, ull a1, ull a2, ull a3) {
    ull s0, s1, s;
    asm("add.rn.f32x2 %0, %1, %2;" : "=l"(s0) : "l"(a0), "l"(a1));
    asm("add.rn.f32x2 %0, %1, %2;" : "=l"(s1) : "l"(a2), "l"(a3));
    asm("add.rn.f32x2 %0, %1, %2;" : "=l"(s)  : "l"(s0), "l"(s1));
    float lo, hi;
    asm("mov.b64 {%0,%1}, %2;" : "=f"(lo), "=f"(hi) : "l"(s));
    return lo + hi;
}
__device__ __forceinline__ float fast_ex2(float x) {
    float r; asm("ex2.approx.f32 %0, %1;" : "=f"(r) : "f"(x)); return r;
}
__device__ __forceinline__ float fast_rcp(float x) {
    float r; asm("rcp.approx.f32 %0, %1;" : "=f"(r) : "f"(x)); return r;
}

// ---------------- cross-CTA sync ----------------
__device__ __forceinline__ int ld_acq(const int* p) {
    int v; asm volatile("ld.global.acquire.gpu.b32 %0, [%1];" : "=r"(v) : "l"(p)); return v;
}
__device__ __forceinline__ void st_rel(int* p, int v) {
    asm volatile("st.global.release.gpu.b32 [%0], %1;" :: "l"(p), "r"(v) : "memory");
}

// 64-dot of packed weight row w[32] against smem vector (used by stage B).
__device__ __forceinline__ float dot64(const ull* __restrict__ w, const float* __restrict__ hvec) {
    ull a0 = 0ull, a1 = 0ull, a2 = 0ull, a3 = 0ull;
    const ulonglong2* hp = (const ulonglong2*)hvec;
#pragma unroll
    for (int i = 0; i < 16; i += 2) {
        ulonglong2 va = hp[i];
        ulonglong2 vb = hp[i + 1];
        ffma2(a0, w[2 * i],     va.x);
        ffma2(a1, w[2 * i + 1], va.y);
        ffma2(a2, w[2 * i + 2], vb.x);
        ffma2(a3, w[2 * i + 3], vb.y);
    }
    return hsum4(a0, a1, a2, a3);
}

// ---------------- init: reset cross-CTA sync state (graph replays!) ----------------
__global__ void init_sync_kernel() {
    int i = blockIdx.x * blockDim.x + threadIdx.x;
    if (i == 0) g_progA = 0;
    if (i < NCHUNKS) g_chunk_done[i] = 0;
}

// ---------------- phase 1: layer0 input-side preactivations ----------------
__global__ __launch_bounds__(256)
void pre0_kernel(const float* __restrict__ y,
                 const float* __restrict__ Wih0,
                 const float* __restrict__ bih0,
                 const float* __restrict__ bhh0)
{
    __shared__ float sy[PRE_TCHUNK + 8];
    const int r = threadIdx.x;
    const int t0 = blockIdx.x * PRE_TCHUNK;
    int t1 = t0 + PRE_TCHUNK; if (t1 > TM1) t1 = TM1;

    for (int i = r; i < PRE_TCHUNK + 5; i += 256) {
        int idx = t0 + i;                    // padded index
        sy[i] = (idx < 5) ? 1.0f : y[idx - 5];
    }

    float w[6];
#pragma unroll
    for (int j = 0; j < 6; j++) w[j] = Wih0[r * 6 + j];
    const float b = bih0[r] + bhh0[r];
    __syncthreads();

    for (int t = t0; t < t1; t++) {
        float acc = b;
#pragma unroll
        for (int j = 0; j < 6; j++)
            acc = fmaf(w[j], sy[t - t0 + j], acc);
        g_pre0[(size_t)t * 256 + r] = acc;
    }
}

// ============ recurrence core: 4 warps, 2 units per lane ============
// Warp wv owns units 16wv..16wv+15. Lane l: gate g=l>>3, units u0=16wv+(l&7), u1=u0+8.
// All 4 gates of u0 and u1 are intra-warp -> shfl exchange, one __syncthreads()/step.
// Activation scale am is pre-folded into weights and the pre stream.
#define LOG2E    1.4426950408889634f
#define TWOLOG2E 2.8853900817779268f

template<bool IS_C>
__device__ void recurrence(const float* __restrict__ Whh,
                           const float* __restrict__ preBuf,
                           float* __restrict__ hTrace)
{
    __shared__ __align__(16) float shb[2][64];
    const int tid = threadIdx.x;          // 0..127 (warps 4-7 exited in dispatcher)
    const int wv  = tid >> 5;
    const int l   = tid & 31;
    const int g   = l >> 3;
    const int k   = l & 7;
    const int u0  = 16 * wv + k;
    const int u1  = u0 + 8;
    const int r0  = 64 * g + u0;
    const int r1  = 64 * g + u1;

    // per-lane activation constants: g==2 -> tanh, else sigmoid
    const float am = (g == 2) ? TWOLOG2E : -LOG2E;
    const float aa = (g == 2) ? 1.0f : 0.0f;
    const float ab = (g == 2) ? -2.0f : 1.0f;

    // weights, pre-scaled by am (removes FMUL before ex2 on critical path)
    ull w0[32], w1[32];
    {
        const float2* p0 = (const float2*)(Whh + r0 * 64);
        const float2* p1 = (const float2*)(Whh + r1 * 64);
#pragma unroll
        for (int i = 0; i < 32; i++) {
            float2 f = p0[i]; w0[i] = packf2(am * f.x, am * f.y);
        }
#pragma unroll
        for (int i = 0; i < 32; i++) {
            float2 f = p1[i]; w1[i] = packf2(am * f.x, am * f.y);
        }
    }

    if (g == 0) { shb[0][u0] = 0.0f; shb[0][u1] = 0.0f; }
    float c0 = 0.0f, c1 = 0.0f;

    if (IS_C) {  // wait for first pre1 chunk
        while (ld_acq(&g_chunk_done[0]) == 0) __nanosleep(256);
    }
    // depth-2 prefetch of the pre stream, am-scaled off the critical path
    float p00 = am * preBuf[r0],        p01 = am * preBuf[r1];
    float p10 = am * preBuf[256 + r0],  p11 = am * preBuf[256 + r1];
    __syncthreads();

    for (int t = 0; t < TM1; t++) {
        const int tf = t + 2;
        if (IS_C) {
            if (tf < TM1 && (tf & (CHUNK - 1)) == 0) {
                const int ch = tf >> 8;
                while (ld_acq(&g_chunk_done[ch]) == 0) __nanosleep(128);
            }
        }
        const float q0 = preBuf[(size_t)tf * 256 + r0];   // padded buffer: no clamp
        const float q1 = preBuf[(size_t)tf * 256 + r1];

        const float* rd = shb[t & 1];
        float*       wr = shb[(t + 1) & 1];

        // ---- two 64-dots sharing the h loads ----
        ull a0 = 0ull, a1 = 0ull, a2 = 0ull, a3 = 0ull;
        ull b0 = 0ull, b1 = 0ull, b2 = 0ull, b3 = 0ull;
        {
            const ulonglong2* hp = (const ulonglong2*)rd;
#pragma unroll
            for (int i = 0; i < 16; i += 2) {
                ulonglong2 va = hp[i];
                ulonglong2 vb = hp[i + 1];
                ffma2(a0, w0[2 * i],     va.x);
                ffma2(a1, w0[2 * i + 1], va.y);
                ffma2(a2, w0[2 * i + 2], vb.x);
                ffma2(a3, w0[2 * i + 3], vb.y);
                ffma2(b0, w1[2 * i],     va.x);
                ffma2(b1, w1[2 * i + 1], va.y);
                ffma2(b2, w1[2 * i + 2], vb.x);
                ffma2(b3, w1[2 * i + 3], vb.y);
            }
        }
        const float v0 = hsum4(a0, a1, a2, a3) + p00;   // already am-scaled
        const float v1 = hsum4(b0, b1, b2, b3) + p01;

        // gate nonlinearity: act = aa + ab*rcp(ex2(v)+1)
        const float act0 = fmaf(ab, fast_rcp(fast_ex2(v0) + 1.0f), aa);
        const float act1 = fmaf(ab, fast_rcp(fast_ex2(v1) + 1.0f), aa);

        // gather the 4 gates of each unit (intra-warp, independent shfls)
        const float gi0 = __shfl_sync(0xffffffffu, act0, k);
        const float gf0 = __shfl_sync(0xffffffffu, act0, k + 8);
        const float gg0 = __shfl_sync(0xffffffffu, act0, k + 16);
        const float go0 = __shfl_sync(0xffffffffu, act0, k + 24);
        const float gi1 = __shfl_sync(0xffffffffu, act1, k);
        const float gf1 = __shfl_sync(0xffffffffu, act1, k + 8);
        const float gg1 = __shfl_sync(0xffffffffu, act1, k + 16);
        const float go1 = __shfl_sync(0xffffffffu, act1, k + 24);

        c0 = fmaf(gf0, c0, gi0 * gg0);
        c1 = fmaf(gf1, c1, gi1 * gg1);
        // h = go * tanh(c) = go - 2go * rcp(ex2(2log2e*c)+1)   (2go off-path)
        const float tg0 = 2.0f * go0, tg1 = 2.0f * go1;
        const float h0 = fmaf(-tg0, fast_rcp(fast_ex2(TWOLOG2E * c0) + 1.0f), go0);
        const float h1 = fmaf(-tg1, fast_rcp(fast_ex2(TWOLOG2E * c1) + 1.0f), go1);

        if (g == 0) {                          // predicated short stores
            wr[u0] = h0;
            wr[u1] = h1;
            hTrace[(size_t)t * 64 + u0] = h0;
            hTrace[(size_t)t * 64 + u1] = h1;
        }
        __syncthreads();

        if (!IS_C) {
            if (((t & 63) == 63) && tid == 0) {   // publish progress
                __threadfence();
                st_rel(&g_progA, t + 1);
            }
        }
        p00 = p10; p01 = p11;
        p10 = am * q0; p11 = am * q1;
    }
    if (!IS_C) {
        if (tid == 0) { __threadfence(); st_rel(&g_progA, TM1); }
    }
}

// ---------------- stage B: pre1[t] = b1 + W_ih1 . h0[t]  (NB trailing CTAs) ----------------
__device__ void stageB(int helper,
                       const float* __restrict__ Wih1,
                       const float* __restrict__ bih1,
                       const float* __restrict__ bhh1)
{
    __shared__ __align__(16) float sh[64 * 64];   // 64-step tile of h0
    const int r = threadIdx.x;

    ull w[32];
    {
        const ull* p = (const ull*)(Wih1 + r * 64);
#pragma unroll
        for (int i = 0; i < 32; i++) w[i] = p[i];
    }
    const float b1 = bih1[r] + bhh1[r];

    for (int c = helper; c < NCHUNKS; c += NB) {
        const int t0 = c * CHUNK;
        int t1 = t0 + CHUNK; if (t1 > TM1) t1 = TM1;

        while (ld_acq(&g_progA) < t1) __nanosleep(256);

        for (int tb = t0; tb < t1; tb += 64) {
            const int cnt = min(64, t1 - tb);
            __syncthreads();
            for (int i = r; i < cnt * 64; i += 256)
                sh[i] = g_h0[(size_t)tb * 64 + i];
            __syncthreads();
            for (int tt = 0; tt < cnt; tt++)
                g_pre1[(size_t)(tb + tt) * 256 + r] = b1 + dot64(w, sh + tt * 64);
        }
        __syncthreads();
        if (r == 0) { __threadfence(); st_rel(&g_chunk_done[c], 1); }
    }
}

// ---------------- pipelined serial phase: 8 co-resident CTAs ----------------
__global__ __launch_bounds__(256, 1)
void lstm_pipe_kernel(const float* __restrict__ Whh0,
                      const float* __restrict__ Wih1,
                      const float* __restrict__ Whh1,
                      const float* __restrict__ bih1,
                      const float* __restrict__ bhh1)
{
    if (blockIdx.x == 0) {
        if (threadIdx.x >= 128) return;       // bar.sync 0 counts non-exited threads
        recurrence<false>(Whh0, g_pre0, g_h0);
    } else if (blockIdx.x == 1) {
        if (threadIdx.x >= 128) return;
        recurrence<true >(Whh1, g_pre1, g_h2);
    } else {
        stageB(blockIdx.x - 2, Wih1, bih1, bhh1);
    }
}

// ---------------- phase 3: parallel FC head ----------------
__global__ __launch_bounds__(256)
void fc_kernel(const float* __restrict__ Wfc,
               const float* __restrict__ bfc,
               float* __restrict__ out)
{
    __shared__ float sWT[64 * 64];
    __shared__ float sh[64 * 64];

    const int tid = threadIdx.x;
    for (int i = tid; i < 4096; i += 256) {
        int n = i >> 6, k = i & 63;
        sWT[k * 64 + n] = Wfc[i];
    }
    const int tbase = blockIdx.x * 64;
    for (int i = tid; i < 4096; i += 256) {
        int tt = i >> 6, k = i & 63;
        int t = tbase + tt;
        sh[i] = (t < TM1) ? g_h2[(size_t)t * 64 + k] : 0.0f;
    }
    __syncthreads();

    const int n = tid & 63;
    const float bb = bfc[n];
    for (int tt = tid >> 6; tt < 64; tt += 4) {
        const int t = tbase + tt;
        if (t >= TM1) break;
        float acc = bb;
#pragma unroll
        for (int k = 0; k < 64; k++)
            acc = fmaf(sh[tt * 64 + k], sWT[k * 64 + n], acc);
        out[(size_t)t * 64 + n] = acc;
    }
}

// ---------------- launch ----------------
extern "C" void kernel_launch(void* const* d_in, const int* in_sizes, int n_in,
                              void* d_out, int out_size)
{
    const float* y    = (const float*)d_in[0];
    const float* Wih0 = (const float*)d_in[1];
    const float* Whh0 = (const float*)d_in[2];
    const float* bih0 = (const float*)d_in[3];
    const float* bhh0 = (const float*)d_in[4];
    const float* Wih1 = (const float*)d_in[5];
    const float* Whh1 = (const float*)d_in[6];
    const float* bih1 = (const float*)d_in[7];
    const float* bhh1 = (const float*)d_in[8];
    const float* Wfc  = (const float*)d_in[9];
    const float* bfc  = (const float*)d_in[10];
    float* out = (float*)d_out;

    init_sync_kernel<<<4, 256>>>();
    const int preblocks = (TM1 + PRE_TCHUNK - 1) / PRE_TCHUNK;
    pre0_kernel<<<preblocks, 256>>>(y, Wih0, bih0, bhh0);
    lstm_pipe_kernel<<<GRID_MEGA, 256>>>(Whh0, Wih1, Whh1, bih1, bhh1);
    fc_kernel<<<(TM1 + 63) / 64, 256>>>(Wfc, bfc, out);
}

// round 11
// speedup vs baseline: 1.6112x; 1.4169x over previous
#include <cuda_runtime.h>
#include <cstdint>

#define TM1 262143            // T-1 real output timesteps
#define RTILE 8               // recurrence pre-staging tile (steps)
#define NTILES_R 32768        // 32768*8 = 262144 steps (1 pad step)
#define PRE_TCHUNK 128
#define CHUNK 256             // stage-B chunk (steps)
#define NCHUNKS ((TM1 + CHUNK - 1) / CHUNK)   // 1024
#define NB 6                  // stage-B helper CTAs
#define GRID_MEGA (2 + NB)

typedef unsigned long long ull;

// Scratch. pre buffers padded one extra tile (+16 steps) so the tile prefetch
// never branches; h traces padded for the single pad step. Pads stay zero.
__device__ float g_pre0[(size_t)(TM1 + 2 * RTILE + 2) * 256];
__device__ float g_h0[(size_t)(TM1 + 16) * 64];
__device__ float g_pre1[(size_t)(TM1 + 2 * RTILE + 2) * 256];
__device__ float g_h2[(size_t)(TM1 + 16) * 64];
__device__ int   g_progA;
__device__ int   g_chunk_done[NCHUNKS];

// ---------------- fast math helpers ----------------
__device__ __forceinline__ void ffma2(ull& acc, ull a, ull b) {
    asm("fma.rn.f32x2 %0, %1, %2, %0;" : "+l"(acc) : "l"(a), "l"(b));
}
__device__ __forceinline__ float hsum4(ull a0, ull a1, ull a2, ull a3) {
    ull s0, s1, s;
    asm("add.rn.f32x2 %0, %1, %2;" : "=l"(s0) : "l"(a0), "l"(a1));
    asm("add.rn.f32x2 %0, %1, %2;" : "=l"(s1) : "l"(a2), "l"(a3));
    asm("add.rn.f32x2 %0, %1, %2;" : "=l"(s)  : "l"(s0), "l"(s1));
    float lo, hi;
    asm("mov.b64 {%0,%1}, %2;" : "=f"(lo), "=f"(hi) : "l"(s));
    return lo + hi;
}
__device__ __forceinline__ float fast_ex2(float x) {
    float r; asm("ex2.approx.f32 %0, %1;" : "=f"(r) : "f"(x)); return r;
}
__device__ __forceinline__ float fast_rcp(float x) {
    float r; asm("rcp.approx.f32 %0, %1;" : "=f"(r) : "f"(x)); return r;
}

// ---------------- cross-CTA sync ----------------
__device__ __forceinline__ int ld_acq(const int* p) {
    int v; asm volatile("ld.global.acquire.gpu.b32 %0, [%1];" : "=r"(v) : "l"(p)); return v;
}
__device__ __forceinline__ void st_rel(int* p, int v) {
    asm volatile("st.global.release.gpu.b32 [%0], %1;" :: "l"(p), "r"(v) : "memory");
}

// ---------------- cp.async (LDGSTS) ----------------
__device__ __forceinline__ void cpasync16(unsigned int sdst, const void* gsrc) {
    asm volatile("cp.async.cg.shared.global [%0], [%1], 16;" :: "r"(sdst), "l"(gsrc));
}
__device__ __forceinline__ void cpasync_commit() {
    asm volatile("cp.async.commit_group;" ::: "memory");
}
__device__ __forceinline__ void cpasync_wait_all() {
    asm volatile("cp.async.wait_group 0;" ::: "memory");
}

// 64-dot of packed weight row w[32] against 16B-aligned smem vector (broadcast loads).
__device__ __forceinline__ float dot64(const ull* __restrict__ w, const float* __restrict__ hvec) {
    ull a0 = 0ull, a1 = 0ull, a2 = 0ull, a3 = 0ull;
    const ulonglong2* hp = (const ulonglong2*)hvec;
#pragma unroll
    for (int i = 0; i < 16; i += 2) {
        ulonglong2 va = hp[i];
        ulonglong2 vb = hp[i + 1];
        ffma2(a0, w[2 * i],     va.x);
        ffma2(a1, w[2 * i + 1], va.y);
        ffma2(a2, w[2 * i + 2], vb.x);
        ffma2(a3, w[2 * i + 3], vb.y);
    }
    return hsum4(a0, a1, a2, a3);
}

// ---------------- init: reset cross-CTA sync state (graph replays!) ----------------
__global__ void init_sync_kernel() {
    int i = blockIdx.x * blockDim.x + threadIdx.x;
    if (i == 0) g_progA = 0;
    if (i < NCHUNKS) g_chunk_done[i] = 0;
}

// ---------------- phase 1: layer0 input-side preactivations ----------------
__global__ __launch_bounds__(256)
void pre0_kernel(const float* __restrict__ y,
                 const float* __restrict__ Wih0,
                 const float* __restrict__ bih0,
                 const float* __restrict__ bhh0)
{
    __shared__ float sy[PRE_TCHUNK + 8];
    const int r = threadIdx.x;
    const int t0 = blockIdx.x * PRE_TCHUNK;
    int t1 = t0 + PRE_TCHUNK; if (t1 > TM1) t1 = TM1;

    for (int i = r; i < PRE_TCHUNK + 5; i += 256) {
        int idx = t0 + i;                    // padded index
        sy[i] = (idx < 5) ? 1.0f : y[idx - 5];
    }

    float w[6];
#pragma unroll
    for (int j = 0; j < 6; j++) w[j] = Wih0[r * 6 + j];
    const float b = bih0[r] + bhh0[r];
    __syncthreads();

    for (int t = t0; t < t1; t++) {
        float acc = b;
#pragma unroll
        for (int j = 0; j < 6; j++)
            acc = fmaf(w[j], sy[t - t0 + j], acc);
        g_pre0[(size_t)t * 256 + r] = acc;
    }
}

// ============ recurrence core (R5 structure + cp.async pre staging) ============
// Lane mapping: warp w, lane l -> gate g=l>>3, unit u=8w+(l&7), gate-row r=64g+u.
// pre stream staged into smem in 8-step tiles via cp.async, double-buffered:
// wait for a tile happens ~8 steps after its issue -> DRAM latency fully hidden.
#define LOG2E    1.4426950408889634f
#define TWOLOG2E 2.8853900817779268f

template<bool IS_C>
__device__ void recurrence(const float* __restrict__ Whh,
                           const float* __restrict__ preBuf,
                           float* __restrict__ hTrace)
{
    __shared__ __align__(16) float shb[2][64];
    __shared__ __align__(16) float spre[2][RTILE * 256];   // 2 x 8KB
    const int tid = threadIdx.x;
    const int wv  = tid >> 5;
    const int l   = tid & 31;
    const int g   = l >> 3;
    const int u8  = l & 7;
    const int u   = 8 * wv + u8;
    const int r   = 64 * g + u;

    ull w[32];
    {
        const ull* p = (const ull*)(Whh + r * 64);
#pragma unroll
        for (int i = 0; i < 32; i++) w[i] = p[i];
    }
    // per-lane activation constants: g==2 -> tanh, else sigmoid
    const float am = (g == 2) ? TWOLOG2E : -LOG2E;
    const float aa = (g == 2) ? 1.0f : 0.0f;
    const float ab = (g == 2) ? -2.0f : 1.0f;

    if (l < 8) shb[0][u] = 0.0f;
    float c = 0.0f;

    if (IS_C) {  // pre1 tile 0 lives in chunk 0
        while (ld_acq(&g_chunk_done[0]) == 0) __nanosleep(256);
    }
    // prologue: stage tile 0
    {
        const float* src = preBuf + (size_t)tid * 4;
        unsigned int d = (unsigned int)__cvta_generic_to_shared(&spre[0][0]);
        cpasync16(d + tid * 16, src);
        cpasync16(d + (tid + 256) * 16, src + 1024);
        cpasync_commit();
        cpasync_wait_all();
    }
    __syncthreads();

    float* hp = hTrace + u;

    for (int tile = 0; tile < NTILES_R; tile++) {
        // stage-C: before prefetching tile+1, ensure its chunk is published
        if (IS_C) {
            if (((tile + 1) & 31) == 0) {      // chunk boundary every 32 tiles
                int ch = (tile + 1) >> 5;
                if (ch > NCHUNKS - 1) ch = NCHUNKS - 1;
                while (ld_acq(&g_chunk_done[ch]) == 0) __nanosleep(128);
            }
        }
        // issue prefetch of tile+1 into the other buffer (waited ~8 steps later)
        {
            const float* src = preBuf + (size_t)(tile + 1) * (RTILE * 256) + tid * 4;
            unsigned int d = (unsigned int)__cvta_generic_to_shared(&spre[(tile + 1) & 1][0]);
            cpasync16(d + tid * 16, src);
            cpasync16(d + (tid + 256) * 16, src + 1024);
            cpasync_commit();
        }

        const float* pt = &spre[tile & 1][r];
#pragma unroll
        for (int s = 0; s < RTILE; s++) {
            const float pre = pt[s * 256];            // conflict-free LDS, off-path
            const float v = pre + dot64(w, shb[s & 1]);

            const float e   = fast_ex2(am * v);
            const float act = fmaf(ab, fast_rcp(e + 1.0f), aa);
            const float gi = __shfl_sync(0xffffffffu, act, u8);
            const float gf = __shfl_sync(0xffffffffu, act, u8 + 8);
            const float gg = __shfl_sync(0xffffffffu, act, u8 + 16);
            const float go = __shfl_sync(0xffffffffu, act, u8 + 24);
            c = fmaf(gf, c, gi * gg);
            const float e2 = fast_ex2(TWOLOG2E * c);
            const float th = fmaf(-2.0f, fast_rcp(e2 + 1.0f), 1.0f);
            const float h  = go * th;

            if (l < 8) {                              // predicated short stores
                shb[(s + 1) & 1][u] = h;
                hp[s * 64] = h;
            }
            __syncthreads();
        }
        hp += RTILE * 64;

        cpasync_wait_all();      // tile+1 staged (issued ~8 steps ago)
        __syncthreads();         // make it visible CTA-wide

        if (!IS_C) {
            if (((tile & 7) == 7) && tid == 0) {      // publish every 64 steps
                __threadfence();
                st_rel(&g_progA, (tile + 1) * RTILE);
            }
        }
    }
}

// ---------------- stage B: pre1[t] = b1 + W_ih1 . h0[t]  (NB trailing CTAs) ----------------
__device__ void stageB(int helper,
                       const float* __restrict__ Wih1,
                       const float* __restrict__ bih1,
                       const float* __restrict__ bhh1)
{
    __shared__ __align__(16) float sh[64 * 64];   // 64-step tile of h0
    const int r = threadIdx.x;

    ull w[32];
    {
        const ull* p = (const ull*)(Wih1 + r * 64);
#pragma unroll
        for (int i = 0; i < 32; i++) w[i] = p[i];
    }
    const float b1 = bih1[r] + bhh1[r];

    for (int c = helper; c < NCHUNKS; c += NB) {
        const int t0 = c * CHUNK;
        int t1 = t0 + CHUNK; if (t1 > TM1) t1 = TM1;

        while (ld_acq(&g_progA) < t1) __nanosleep(256);

        for (int tb = t0; tb < t1; tb += 64) {
            const int cnt = min(64, t1 - tb);
            __syncthreads();
            for (int i = r; i < cnt * 64; i += 256)
                sh[i] = g_h0[(size_t)tb * 64 + i];
            __syncthreads();
            for (int tt = 0; tt < cnt; tt++)
                g_pre1[(size_t)(tb + tt) * 256 + r] = b1 + dot64(w, sh + tt * 64);
        }
        __syncthreads();
        if (r == 0) { __threadfence(); st_rel(&g_chunk_done[c], 1); }
    }
}

// ---------------- pipelined serial phase: 8 co-resident CTAs ----------------
__global__ __launch_bounds__(256, 1)
void lstm_pipe_kernel(const float* __restrict__ Whh0,
                      const float* __restrict__ Wih1,
                      const float* __restrict__ Whh1,
                      const float* __restrict__ bih1,
                      const float* __restrict__ bhh1)
{
    if (blockIdx.x == 0)       recurrence<false>(Whh0, g_pre0, g_h0);
    else if (blockIdx.x == 1)  recurrence<true >(Whh1, g_pre1, g_h2);
    else                       stageB(blockIdx.x - 2, Wih1, bih1, bhh1);
}

// ---------------- phase 3: parallel FC head ----------------
__global__ __launch_bounds__(256)
void fc_kernel(const float* __restrict__ Wfc,
               const float* __restrict__ bfc,
               float* __restrict__ out)
{
    __shared__ float sWT[64 * 64];
    __shared__ float sh[64 * 64];

    const int tid = threadIdx.x;
    for (int i = tid; i < 4096; i += 256) {
        int n = i >> 6, k = i & 63;
        sWT[k * 64 + n] = Wfc[i];
    }
    const int tbase = blockIdx.x * 64;
    for (int i = tid; i < 4096; i += 256) {
        int tt = i >> 6, k = i & 63;
        int t = tbase + tt;
        sh[i] = (t < TM1) ? g_h2[(size_t)t * 64 + k] : 0.0f;
    }
    __syncthreads();

    const int n = tid & 63;
    const float bb = bfc[n];
    for (int tt = tid >> 6; tt < 64; tt += 4) {
        const int t = tbase + tt;
        if (t >= TM1) break;
        float acc = bb;
#pragma unroll
        for (int k = 0; k < 64; k++)
            acc = fmaf(sh[tt * 64 + k], sWT[k * 64 + n], acc);
        out[(size_t)t * 64 + n] = acc;
    }
}

// ---------------- launch ----------------
extern "C" void kernel_launch(void* const* d_in, const int* in_sizes, int n_in,
                              void* d_out, int out_size)
{
    const float* y    = (const float*)d_in[0];
    const float* Wih0 = (const float*)d_in[1];
    const float* Whh0 = (const float*)d_in[2];
    const float* bih0 = (const float*)d_in[3];
    const float* bhh0 = (const float*)d_in[4];
    const float* Wih1 = (const float*)d_in[5];
    const float* Whh1 = (const float*)d_in[6];
    const float* bih1 = (const float*)d_in[7];
    const float* bhh1 = (const float*)d_in[8];
    const float* Wfc  = (const float*)d_in[9];
    const float* bfc  = (const float*)d_in[10];
    float* out = (float*)d_out;

    init_sync_kernel<<<4, 256>>>();
    const int preblocks = (TM1 + PRE_TCHUNK - 1) / PRE_TCHUNK;
    pre0_kernel<<<preblocks, 256>>>(y, Wih0, bih0, bhh0);
    lstm_pipe_kernel<<<GRID_MEGA, 256>>>(Whh0, Wih1, Whh1, bih1, bhh1);
    fc_kernel<<<(TM1 + 63) / 64, 256>>>(Wfc, bfc, out);
}

// round 12
// speedup vs baseline: 1.6666x; 1.0343x over previous
#include <cuda_runtime.h>
#include <cstdint>

#define TM1 262143            // T-1 real output timesteps
#define RTILE 16              // recurrence pre-staging tile (steps)
#define NTILES_R 16384        // 16384*16 = 262144 steps (1 pad step)
#define PRE_TCHUNK 128
#define CHUNK 256             // stage-B chunk (steps)
#define NCHUNKS ((TM1 + CHUNK - 1) / CHUNK)   // 1024
#define NB 6                  // stage-B helper CTAs
#define GRID_MEGA (2 + NB)

typedef unsigned long long ull;

// Scratch. pre buffers padded one extra tile (+32 steps) so the tile prefetch
// never branches; h traces padded for the single pad step. Pads stay zero.
__device__ float g_pre0[(size_t)(TM1 + 2 * RTILE + 2) * 256];
__device__ float g_h0[(size_t)(TM1 + 32) * 64];
__device__ float g_pre1[(size_t)(TM1 + 2 * RTILE + 2) * 256];
__device__ float g_h2[(size_t)(TM1 + 32) * 64];
__device__ int   g_progA;
__device__ int   g_chunk_done[NCHUNKS];

#define LOG2E    1.4426950408889634f
#define TWOLOG2E 2.8853900817779268f

// ---------------- fast math helpers ----------------
__device__ __forceinline__ void ffma2(ull& acc, ull a, ull b) {
    asm("fma.rn.f32x2 %0, %1, %2, %0;" : "+l"(acc) : "l"(a), "l"(b));
}
__device__ __forceinline__ ull packf2(float x, float y) {
    ull r; asm("mov.b64 %0, {%1, %2};" : "=l"(r) : "f"(x), "f"(y)); return r;
}
__device__ __forceinline__ float hsum4(ull a0, ull a1, ull a2, ull a3) {
    ull s0, s1, s;
    asm("add.rn.f32x2 %0, %1, %2;" : "=l"(s0) : "l"(a0), "l"(a1));
    asm("add.rn.f32x2 %0, %1, %2;" : "=l"(s1) : "l"(a2), "l"(a3));
    asm("add.rn.f32x2 %0, %1, %2;" : "=l"(s)  : "l"(s0), "l"(s1));
    float lo, hi;
    asm("mov.b64 {%0,%1}, %2;" : "=f"(lo), "=f"(hi) : "l"(s));
    return lo + hi;
}
__device__ __forceinline__ float fast_ex2(float x) {
    float r; asm("ex2.approx.f32 %0, %1;" : "=f"(r) : "f"(x)); return r;
}
__device__ __forceinline__ float fast_rcp(float x) {
    float r; asm("rcp.approx.f32 %0, %1;" : "=f"(r) : "f"(x)); return r;
}

// ---------------- cross-CTA sync ----------------
__device__ __forceinline__ int ld_acq(const int* p) {
    int v; asm volatile("ld.global.acquire.gpu.b32 %0, [%1];" : "=r"(v) : "l"(p)); return v;
}
__device__ __forceinline__ void st_rel(int* p, int v) {
    asm volatile("st.global.release.gpu.b32 [%0], %1;" :: "l"(p), "r"(v) : "memory");
}

// ---------------- cp.async (LDGSTS) ----------------
__device__ __forceinline__ void cpasync16(unsigned int sdst, const void* gsrc) {
    asm volatile("cp.async.cg.shared.global [%0], [%1], 16;" :: "r"(sdst), "l"(gsrc));
}
__device__ __forceinline__ void cpasync_commit() {
    asm volatile("cp.async.commit_group;" ::: "memory");
}
__device__ __forceinline__ void cpasync_wait_all() {
    asm volatile("cp.async.wait_group 0;" ::: "memory");
}

// 64-dot of packed weight row w[32] against 16B-aligned smem vector (broadcast loads).
__device__ __forceinline__ float dot64(const ull* __restrict__ w, const float* __restrict__ hvec) {
    ull a0 = 0ull, a1 = 0ull, a2 = 0ull, a3 = 0ull;
    const ulonglong2* hp = (const ulonglong2*)hvec;
#pragma unroll
    for (int i = 0; i < 16; i += 2) {
        ulonglong2 va = hp[i];
        ulonglong2 vb = hp[i + 1];
        ffma2(a0, w[2 * i],     va.x);
        ffma2(a1, w[2 * i + 1], va.y);
        ffma2(a2, w[2 * i + 2], vb.x);
        ffma2(a3, w[2 * i + 3], vb.y);
    }
    return hsum4(a0, a1, a2, a3);
}

// ---------------- init: reset cross-CTA sync state (graph replays!) ----------------
__global__ void init_sync_kernel() {
    int i = blockIdx.x * blockDim.x + threadIdx.x;
    if (i == 0) g_progA = 0;
    if (i < NCHUNKS) g_chunk_done[i] = 0;
}

// ---------------- phase 1: layer0 input-side preactivations (am-prescaled) ----------------
__global__ __launch_bounds__(256)
void pre0_kernel(const float* __restrict__ y,
                 const float* __restrict__ Wih0,
                 const float* __restrict__ bih0,
                 const float* __restrict__ bhh0)
{
    __shared__ float sy[PRE_TCHUNK + 8];
    const int r = threadIdx.x;
    const int t0 = blockIdx.x * PRE_TCHUNK;
    int t1 = t0 + PRE_TCHUNK; if (t1 > TM1) t1 = TM1;

    for (int i = r; i < PRE_TCHUNK + 5; i += 256) {
        int idx = t0 + i;                    // padded index
        sy[i] = (idx < 5) ? 1.0f : y[idx - 5];
    }

    float w[6];
#pragma unroll
    for (int j = 0; j < 6; j++) w[j] = Wih0[r * 6 + j];
    const float b = bih0[r] + bhh0[r];
    // activation-scale prefold: gate (r>>6)==2 -> tanh scale, else sigmoid scale
    const float am = ((r >> 6) == 2) ? TWOLOG2E : -LOG2E;
    __syncthreads();

    for (int t = t0; t < t1; t++) {
        float acc = b;
#pragma unroll
        for (int j = 0; j < 6; j++)
            acc = fmaf(w[j], sy[t - t0 + j], acc);
        g_pre0[(size_t)t * 256 + r] = am * acc;
    }
}

// ============ recurrence core (cp.async staging, am-prescaled inputs) ============
// Lane mapping: warp w, lane l -> gate g=l>>3, unit u=8w+(l&7), gate-row r=64g+u.
// pre stream (already am-scaled) staged into smem in 16-step tiles, double-buffered.
template<bool IS_C>
__device__ void recurrence(const float* __restrict__ Whh,
                           const float* __restrict__ preBuf,
                           float* __restrict__ hTrace)
{
    __shared__ __align__(16) float shb[2][64];
    __shared__ __align__(16) float spre[2][RTILE * 256];   // 2 x 16KB
    const int tid = threadIdx.x;
    const int wv  = tid >> 5;
    const int l   = tid & 31;
    const int g   = l >> 3;
    const int u8  = l & 7;
    const int u   = 8 * wv + u8;
    const int r   = 64 * g + u;

    // per-lane activation constants: g==2 -> tanh, else sigmoid
    const float am = (g == 2) ? TWOLOG2E : -LOG2E;
    const float aa = (g == 2) ? 1.0f : 0.0f;
    const float ab = (g == 2) ? -2.0f : 1.0f;

    // weights pre-scaled by am: ex2 input is v directly (no FMUL on critical path)
    ull w[32];
    {
        const float2* p = (const float2*)(Whh + r * 64);
#pragma unroll
        for (int i = 0; i < 32; i++) {
            float2 f = p[i];
            w[i] = packf2(am * f.x, am * f.y);
        }
    }

    if (l < 8) shb[0][u] = 0.0f;
    float c = 0.0f;

    if (IS_C) {  // pre1 tile 0 lives in chunk 0
        while (ld_acq(&g_chunk_done[0]) == 0) __nanosleep(256);
    }
    // prologue: stage tile 0 (RTILE*256 floats = 16KB; 4 x 16B per thread)
    {
        const float* src = preBuf + (size_t)tid * 4;
        unsigned int d = (unsigned int)__cvta_generic_to_shared(&spre[0][0]);
#pragma unroll
        for (int j = 0; j < 4; j++)
            cpasync16(d + (tid + 256 * j) * 16, src + 1024 * j);
        cpasync_commit();
        cpasync_wait_all();
    }
    __syncthreads();

    float* hp = hTrace + u;

    for (int tile = 0; tile < NTILES_R; tile++) {
        // stage-C: before prefetching tile+1, ensure its chunk is published
        if (IS_C) {
            if (((tile + 1) & 15) == 0) {      // chunk boundary every 16 tiles
                int ch = (tile + 1) >> 4;
                if (ch > NCHUNKS - 1) ch = NCHUNKS - 1;
                while (ld_acq(&g_chunk_done[ch]) == 0) __nanosleep(128);
            }
        }
        // issue prefetch of tile+1 into the other buffer (waited ~16 steps later)
        {
            const float* src = preBuf + (size_t)(tile + 1) * (RTILE * 256) + tid * 4;
            unsigned int d = (unsigned int)__cvta_generic_to_shared(&spre[(tile + 1) & 1][0]);
#pragma unroll
            for (int j = 0; j < 4; j++)
                cpasync16(d + (tid + 256 * j) * 16, src + 1024 * j);
            cpasync_commit();
        }

        const float* pt = &spre[tile & 1][r];
#pragma unroll
        for (int s = 0; s < RTILE; s++) {
            const float pre = pt[s * 256];            // conflict-free LDS, off-path
            const float v = pre + dot64(w, shb[s & 1]);   // already am-scaled

            const float e   = fast_ex2(v);
            const float act = fmaf(ab, fast_rcp(e + 1.0f), aa);
            const float gi = __shfl_sync(0xffffffffu, act, u8);
            const float gf = __shfl_sync(0xffffffffu, act, u8 + 8);
            const float gg = __shfl_sync(0xffffffffu, act, u8 + 16);
            const float go = __shfl_sync(0xffffffffu, act, u8 + 24);
            c = fmaf(gf, c, gi * gg);
            const float tg = 2.0f * go;               // off-path (parallel with c fma)
            const float e2 = fast_ex2(TWOLOG2E * c);
            const float h  = fmaf(-tg, fast_rcp(e2 + 1.0f), go);   // go*tanh(c)

            if (l < 8) {                              // predicated short stores
                shb[(s + 1) & 1][u] = h;
                hp[s * 64] = h;
            }
            __syncthreads();
        }
        hp += RTILE * 64;

        cpasync_wait_all();      // tile+1 staged (issued ~16 steps ago)
        __syncthreads();         // make it visible CTA-wide

        if (!IS_C) {
            if (((tile & 3) == 3) && tid == 0) {      // publish every 64 steps
                __threadfence();
                st_rel(&g_progA, (tile + 1) * RTILE);
            }
        }
    }
}

// ---------------- stage B: pre1[t] = am*(b1 + W_ih1 . h0[t])  (NB trailing CTAs) ----------------
__device__ void stageB(int helper,
                       const float* __restrict__ Wih1,
                       const float* __restrict__ bih1,
                       const float* __restrict__ bhh1)
{
    __shared__ __align__(16) float sh[64 * 64];   // 64-step tile of h0
    const int r = threadIdx.x;

    ull w[32];
    {
        const ull* p = (const ull*)(Wih1 + r * 64);
#pragma unroll
        for (int i = 0; i < 32; i++) w[i] = p[i];
    }
    const float b1 = bih1[r] + bhh1[r];
    const float am = ((r >> 6) == 2) ? TWOLOG2E : -LOG2E;   // prescale for recurrence C

    for (int c = helper; c < NCHUNKS; c += NB) {
        const int t0 = c * CHUNK;
        int t1 = t0 + CHUNK; if (t1 > TM1) t1 = TM1;

        while (ld_acq(&g_progA) < t1) __nanosleep(256);

        for (int tb = t0; tb < t1; tb += 64) {
            const int cnt = min(64, t1 - tb);
            __syncthreads();
            for (int i = r; i < cnt * 64; i += 256)
                sh[i] = g_h0[(size_t)tb * 64 + i];
            __syncthreads();
            for (int tt = 0; tt < cnt; tt++)
                g_pre1[(size_t)(tb + tt) * 256 + r] = am * (b1 + dot64(w, sh + tt * 64));
        }
        __syncthreads();
        if (r == 0) { __threadfence(); st_rel(&g_chunk_done[c], 1); }
    }
}

// ---------------- pipelined serial phase: 8 co-resident CTAs ----------------
__global__ __launch_bounds__(256, 1)
void lstm_pipe_kernel(const float* __restrict__ Whh0,
                      const float* __restrict__ Wih1,
                      const float* __restrict__ Whh1,
                      const float* __restrict__ bih1,
                      const float* __restrict__ bhh1)
{
    if (blockIdx.x == 0)       recurrence<false>(Whh0, g_pre0, g_h0);
    else if (blockIdx.x == 1)  recurrence<true >(Whh1, g_pre1, g_h2);
    else                       stageB(blockIdx.x - 2, Wih1, bih1, bhh1);
}

// ---------------- phase 3: parallel FC head ----------------
__global__ __launch_bounds__(256)
void fc_kernel(const float* __restrict__ Wfc,
               const float* __restrict__ bfc,
               float* __restrict__ out)
{
    __shared__ float sWT[64 * 64];
    __shared__ float sh[64 * 64];

    const int tid = threadIdx.x;
    for (int i = tid; i < 4096; i += 256) {
        int n = i >> 6, k = i & 63;
        sWT[k * 64 + n] = Wfc[i];
    }
    const int tbase = blockIdx.x * 64;
    for (int i = tid; i < 4096; i += 256) {
        int tt = i >> 6, k = i & 63;
        int t = tbase + tt;
        sh[i] = (t < TM1) ? g_h2[(size_t)t * 64 + k] : 0.0f;
    }
    __syncthreads();

    const int n = tid & 63;
    const float bb = bfc[n];
    for (int tt = tid >> 6; tt < 64; tt += 4) {
        const int t = tbase + tt;
        if (t >= TM1) break;
        float acc = bb;
#pragma unroll
        for (int k = 0; k < 64; k++)
            acc = fmaf(sh[tt * 64 + k], sWT[k * 64 + n], acc);
        out[(size_t)t * 64 + n] = acc;
    }
}

// ---------------- launch ----------------
extern "C" void kernel_launch(void* const* d_in, const int* in_sizes, int n_in,
                              void* d_out, int out_size)
{
    const float* y    = (const float*)d_in[0];
    const float* Wih0 = (const float*)d_in[1];
    const float* Whh0 = (const float*)d_in[2];
    const float* bih0 = (const float*)d_in[3];
    const float* bhh0 = (const float*)d_in[4];
    const float* Wih1 = (const float*)d_in[5];
    const float* Whh1 = (const float*)d_in[6];
    const float* bih1 = (const float*)d_in[7];
    const float* bhh1 = (const float*)d_in[8];
    const float* Wfc  = (const float*)d_in[9];
    const float* bfc  = (const float*)d_in[10];
    float* out = (float*)d_out;

    init_sync_kernel<<<4, 256>>>();
    const int preblocks = (TM1 + PRE_TCHUNK - 1) / PRE_TCHUNK;
    pre0_kernel<<<preblocks, 256>>>(y, Wih0, bih0, bhh0);
    lstm_pipe_kernel<<<GRID_MEGA, 256>>>(Whh0, Wih1, Whh1, bih1, bhh1);
    fc_kernel<<<(TM1 + 63) / 64, 256>>>(Wfc, bfc, out);
}